// round 6
// baseline (speedup 1.0000x reference)
#include <cuda_runtime.h>
#include <math.h>

// ---------------- problem constants ----------------
#define NB 4096
#define ND 128
#define INV_TEMP 14.285714285714285714f          // 1/0.07
#define KE 20.609929155556619f                   // INV_TEMP * log2(e)
#define LN2 0.69314718055994531f

// ---------------- device scratch (no allocs) ----------------
__device__ float g_Rf[2][NB];
__device__ float g_Rs[2][NB];
__device__ float g_RfM[NB];
__device__ float g_RsM[NB];
__device__ unsigned g_baseBits[32768];           // [256 rows][128 words]
__device__ float g_state[2][NB * 6];             // {Zz, Zm, Sz, Sm, ws, vc}

// ---------------- small helpers ----------------
__device__ __forceinline__ unsigned long long ffma2(unsigned long long a,
                                                    unsigned long long b,
                                                    unsigned long long c) {
    unsigned long long d;
    asm("fma.rn.f32x2 %0, %1, %2, %3;" : "=l"(d) : "l"(a), "l"(b), "l"(c));
    return d;
}
__device__ __forceinline__ float red2(unsigned long long v) {
    float lo = __uint_as_float((unsigned)v);
    float hi = __uint_as_float((unsigned)(v >> 32));
    return lo + hi;
}
__device__ __forceinline__ float ex2f(float x) {
    float r; asm("ex2.approx.ftz.f32 %0, %1;" : "=f"(r) : "f"(x)); return r;
}
__device__ __forceinline__ float lg2f(float x) {
    float r; asm("lg2.approx.ftz.f32 %0, %1;" : "=f"(r) : "f"(x)); return r;
}

// ---------------- smem tile loaders (512-thread blocks) ----------------
// A tile: 64 rows x 128 k -> 64 k-pair slices, pitch 132 floats (528 B).
// Slice p, chunk ch (16B): ch = h*16 + t holds rows rA=4t+2h, rB=4t+2h+1:
//   floats {A[2p][rA], A[2p+1][rA], A[2p][rB], A[2p+1][rB]}.
// Read: thread ty takes chunks ty and 16+ty -> warp (ty 0..15) hits 16
// consecutive 16B chunks per LDS.128 => conflict-free, 2-way tx broadcast.
__device__ __forceinline__ void load_A(float* dst, const float* __restrict__ src,
                                       int g0, int tid) {
    for (int idx = tid; idx < 2048; idx += 512) {
        int row = idx >> 5, dv = idx & 31;
        float4 v = *(const float4*)(src + (size_t)(g0 + row) * ND + (dv << 2));
        int t = row >> 2, h = (row >> 1) & 1, par = row & 1;
        int cbase = ((h << 4) + t) * 4 + par * 2;
        dst[(2 * dv) * 132 + cbase]         = v.x;   // k=4dv
        dst[(2 * dv) * 132 + cbase + 1]     = v.y;   // k=4dv+1
        dst[(2 * dv + 1) * 132 + cbase]     = v.z;   // k=4dv+2
        dst[(2 * dv + 1) * 132 + cbase + 1] = v.w;   // k=4dv+3
    }
}

// B tile: 64 cols x 128 k row-major, pitch 132 floats (16B-aligned rows).
__device__ __forceinline__ void load_B(float* dst, const float* __restrict__ src,
                                       int j0, int tid) {
    for (int idx = tid; idx < 2048; idx += 512) {
        int n = idx >> 5, dv = idx & 31;
        *(float4*)(dst + n * 132 + (dv << 2)) =
            *(const float4*)(src + (size_t)(j0 + n) * ND + (dv << 2));
    }
}

// 64x64x128 gemm, 4x4 per-thread tile, f32x2 FMAs, 256-thread group.
// acc[r*4+c]: f32x2 (even/odd k) accumulator for row ty*4+r, col tx*4+c.
// L-pass then H-pass: no back-to-back RAW on accumulators.
__device__ __forceinline__ void gemm44(const float* __restrict__ A,
                                       const float* __restrict__ B,
                                       int ty, int tx,
                                       unsigned long long acc[16]) {
#pragma unroll
    for (int i = 0; i < 16; i++) acc[i] = 0ull;
    const float* ap = A + ty * 4;
    const float* bp = B + tx * 4 * 132;
#pragma unroll 4
    for (int q = 0; q < 32; q++) {
        const float* s = ap + (2 * q) * 132;
        ulonglong2 c0 = *(const ulonglong2*)(s);          // slice 2q, rows 4ty..4ty+1
        ulonglong2 c1 = *(const ulonglong2*)(s + 64);     // slice 2q, rows 4ty+2..3
        ulonglong2 d0 = *(const ulonglong2*)(s + 132);    // slice 2q+1
        ulonglong2 d1 = *(const ulonglong2*)(s + 196);
        unsigned long long aL[4] = {c0.x, c0.y, c1.x, c1.y};
        unsigned long long aH[4] = {d0.x, d0.y, d1.x, d1.y};
        unsigned long long bL[4], bH[4];
#pragma unroll
        for (int c = 0; c < 4; c++) {
            ulonglong2 cb = *(const ulonglong2*)(bp + c * 132 + 4 * q);
            bL[c] = cb.x; bH[c] = cb.y;
        }
#pragma unroll
        for (int r = 0; r < 4; r++)
#pragma unroll
            for (int c = 0; c < 4; c++)
                acc[r * 4 + c] = ffma2(aL[r], bL[c], acc[r * 4 + c]);
#pragma unroll
        for (int r = 0; r < 4; r++)
#pragma unroll
            for (int c = 0; c < 4; c++)
                acc[r * 4 + c] = ffma2(aH[r], bH[c], acc[r * 4 + c]);
    }
}

// ---------------- kernel 0: pack neglect-base mask to bits ----------------
__global__ void pack_kernel(const float* __restrict__ base) {
    int w = blockIdx.x * 256 + threadIdx.x;     // 32768 words
    const float* p = base + (size_t)w * 32;
    unsigned bits = 0;
#pragma unroll
    for (int b = 0; b < 32; b++) bits |= (p[b] > 0.f) ? (1u << b) : 0u;
    g_baseBits[w] = bits;
}

// ---------------- kernel 1: pool row-maxes ----------------
// grid (64 row-tiles, 2 pool-halves), 512 thr. grp0: f x Pool_ag, grp1: spr x Pool_sp.
__global__ void __launch_bounds__(512, 1)
rmax_kernel(const float* __restrict__ f, const float* __restrict__ spr,
            const float* __restrict__ pag, const float* __restrict__ psp) {
    extern __shared__ float sm[];
    int tid = threadIdx.x;
    int grp = tid >> 8, t = tid & 255, tx = t >> 4, ty = t & 15;
    int g0 = blockIdx.x * 64, p0 = blockIdx.y * 512;
    float* A0 = sm;
    float* A1 = sm + 8448;
    float* B0 = sm + 16896;
    float* B1 = sm + 25344;

    load_A(A0, f, g0, tid);
    load_A(A1, spr, g0, tid);

    float rm[4];
#pragma unroll
    for (int r = 0; r < 4; r++) rm[r] = -1e30f;

    for (int jt = 0; jt < 8; jt++) {
        __syncthreads();
        load_B(B0, pag, p0 + jt * 64, tid);
        load_B(B1, psp, p0 + jt * 64, tid);
        __syncthreads();
        unsigned long long acc[16];
        gemm44(grp ? A1 : A0, grp ? B1 : B0, ty, tx, acc);
#pragma unroll
        for (int r = 0; r < 4; r++)
#pragma unroll
            for (int c = 0; c < 4; c++)
                rm[r] = fmaxf(rm[r], red2(acc[r * 4 + c]));
    }
    __syncthreads();
#pragma unroll
    for (int r = 0; r < 4; r++)
        sm[grp * 1024 + (ty * 4 + r) * 16 + tx] = rm[r];
    __syncthreads();
    if (tid < 64) {
        float mf = -1e30f, ms = -1e30f;
        for (int k = 0; k < 16; k++) {
            mf = fmaxf(mf, sm[tid * 16 + k]);
            ms = fmaxf(ms, sm[1024 + tid * 16 + k]);
        }
        g_Rf[blockIdx.y][g0 + tid] = mf;
        g_Rs[blockIdx.y][g0 + tid] = ms;
    }
}

// ---------------- kernel 1b: merge pool halves ----------------
__global__ void merge_kernel() {
    int i = blockIdx.x * 256 + threadIdx.x;
    g_RfM[i] = fmaxf(g_Rf[0][i], g_Rf[1][i]);
    g_RsM[i] = fmaxf(g_Rs[0][i], g_Rs[1][i]);
}

// ---------------- kernel 2: fused B x B pass ----------------
// grid (64 row-tiles, 2 col-splits), 512 thr = 2 groups x 256.
// Per 64-col j-tile: pass1: grp0 gemm(f)->bitsA/bitsN, grp1 gemm(spr)->bitsE;
// exchange via smem; pass2: grp0 gemm(z), grp1 gemm(zmix) -> LSE + weighted sums.
__global__ void __launch_bounds__(512, 1)
main_kernel(const float* __restrict__ z, const float* __restrict__ spr,
            const float* __restrict__ f, const float* __restrict__ zmix) {
    extern __shared__ float sm[];
    int tid = threadIdx.x;
    int grp = tid >> 8, t = tid & 255, tx = t >> 4, ty = t & 15;
    int g0 = blockIdx.x * 64, col0 = blockIdx.y * 2048;

    float* AF = sm;
    float* ASP = sm + 8448;
    float* AZ = sm + 16896;
    float* AM = sm + 25344;
    float* B0 = sm + 33792;
    float* B1 = sm + 42240;
    unsigned* maskA = (unsigned*)(sm + 50688);
    unsigned* maskN = maskA + 256;
    unsigned* maskE = maskA + 512;

    load_A(AF, f, g0, tid);
    load_A(ASP, spr, g0, tid);
    load_A(AZ, z, g0, tid);
    load_A(AM, zmix, g0, tid);

    const float* Rrow = grp ? g_RsM : g_RfM;
    float Rr[4];
#pragma unroll
    for (int r = 0; r < 4; r++) Rr[r] = Rrow[g0 + ty * 4 + r];

    // grp0: st0=Zz, st1=Sz (+ ws, vc); grp1: st0=Zm, st1=Sm
    float st0[4], st1[4], ws[4], vc[4];
#pragma unroll
    for (int r = 0; r < 4; r++) { st0[r] = 0.f; st1[r] = 0.f; ws[r] = 0.f; vc[r] = 0.f; }

    for (int jt = 0; jt < 32; jt++) {
        int j0 = col0 + jt * 64;

        // ---- pass 1: masks ----
        __syncthreads();
        load_B(B0, f, j0, tid);
        load_B(B1, spr, j0, tid);
        __syncthreads();

        unsigned long long acc[16];
        gemm44(grp ? ASP : AF, grp ? B1 : B0, ty, tx, acc);

        float Rc[4];
#pragma unroll
        for (int c = 0; c < 4; c++) Rc[c] = Rrow[j0 + tx * 4 + c];

        if (grp == 0) {
            int wcol = (j0 + tx * 4) >> 5;
            int shift = (tx * 4) & 31;
            unsigned bA = 0, bN = 0;
#pragma unroll
            for (int r = 0; r < 4; r++) {
                int i = g0 + ty * 4 + r;
                unsigned nbw = (g_baseBits[(i & 255) * 128 + wcol] >> shift) & 15u;
#pragma unroll
                for (int c = 0; c < 4; c++) {
                    float v = red2(acc[r * 4 + c]);
                    bool m1 = (Rr[r] < v) | (Rc[c] < v);
                    bool neq = (i != (j0 + tx * 4 + c));
                    unsigned bit = 1u << (r * 4 + c);
                    if (m1 & neq) bA |= bit;
                    if ((m1 | (((nbw >> c) & 1u) != 0u)) & neq) bN |= bit;
                }
            }
            maskA[t] = bA;
            maskN[t] = bN;
        } else {
            unsigned bE = 0;
#pragma unroll
            for (int r = 0; r < 4; r++) {
                int i = g0 + ty * 4 + r;
#pragma unroll
                for (int c = 0; c < 4; c++) {
                    float v = red2(acc[r * 4 + c]);
                    bool m2 = (Rr[r] < v) | (Rc[c] < v);
                    bool neq = (i != (j0 + tx * 4 + c));
                    if (m2 & neq) bE |= 1u << (r * 4 + c);
                }
            }
            maskE[t] = bE;
        }

        // ---- pass 2: logits ----
        __syncthreads();
        load_B(B0, z, j0, tid);
        load_B(B1, zmix, j0, tid);
        __syncthreads();

        gemm44(grp ? AM : AZ, grp ? B1 : B0, ty, tx, acc);

        unsigned bA = maskA[t], bN = maskN[t], bE = maskE[t];
        if (grp == 0) {
#pragma unroll
            for (int r = 0; r < 4; r++) {
                float pA = (float)__popc((bA >> (4 * r)) & 15u);
                float pE = (float)__popc((bE >> (4 * r)) & 15u);
                vc[r] += pA;
                ws[r] += pA + 0.5f * pE;
            }
        }
#pragma unroll
        for (int r = 0; r < 4; r++) {
#pragma unroll
            for (int c = 0; c < 4; c++) {
                int idx = r * 4 + c;
                float v = red2(acc[idx]);
                float w = (((bA >> idx) & 1u) ? 1.0f : 0.0f) +
                          (((bE >> idx) & 1u) ? 0.5f : 0.0f);
                st1[r] += w * v;
                float e = ex2f(KE * (v - 1.0f));
                st0[r] += ((bN >> idx) & 1u) ? e : 0.f;
            }
        }
    }

    // ---- block reduction across tx ----
    __syncthreads();
    if (grp == 0) {
#pragma unroll
        for (int r = 0; r < 4; r++) {
            int row = ty * 4 + r;
            sm[0 * 1024 + row * 16 + tx] = st0[r];   // Zz
            sm[1 * 1024 + row * 16 + tx] = st1[r];   // Sz
            sm[2 * 1024 + row * 16 + tx] = ws[r];
            sm[3 * 1024 + row * 16 + tx] = vc[r];
        }
    } else {
#pragma unroll
        for (int r = 0; r < 4; r++) {
            int row = ty * 4 + r;
            sm[4 * 1024 + row * 16 + tx] = st0[r];   // Zm
            sm[5 * 1024 + row * 16 + tx] = st1[r];   // Sm
        }
    }
    __syncthreads();
    if (tid < 64) {
        float a[6] = {0.f, 0.f, 0.f, 0.f, 0.f, 0.f};
        for (int k = 0; k < 16; k++)
#pragma unroll
            for (int q = 0; q < 6; q++) a[q] += sm[q * 1024 + tid * 16 + k];
        float* dst = &g_state[blockIdx.y][(size_t)(g0 + tid) * 6];
        dst[0] = a[0];   // Zz
        dst[1] = a[4];   // Zm
        dst[2] = a[1];   // Sz
        dst[3] = a[5];   // Sm
        dst[4] = a[2];   // ws (0.5 factor already applied)
        dst[5] = a[3];   // vc
    }
}

// ---------------- kernel 3: final scalar reduction ----------------
__global__ void reduce_kernel(float* __restrict__ out) {
    __shared__ float s1[256], s2[256];
    int tid = threadIdx.x;
    float grand = 0.f;
    for (int m = 0; m < 16; m++) {
        int i = m * 256 + tid;
        float q[6];
#pragma unroll
        for (int qn = 0; qn < 6; qn++)
            q[qn] = g_state[0][(size_t)i * 6 + qn] + g_state[1][(size_t)i * 6 + qn];
        float Zz = q[0], Zm = q[1], Sz = q[2], Sm = q[3], w = q[4], vcc = q[5];
        float num = 0.f, den = 0.f;
        if (vcc > 0.5f) {
            float lzz = INV_TEMP + LN2 * lg2f(Zz);
            float lzm = INV_TEMP + LN2 * lg2f(Zm);
            num = INV_TEMP * (Sz + Sm) - w * (lzz + lzm);
            den = w;
        }
        s1[tid] = num;
        s2[tid] = den;
        __syncthreads();
        for (int off = 128; off > 0; off >>= 1) {
            if (tid < off) { s1[tid] += s1[tid + off]; s2[tid] += s2[tid + off]; }
            __syncthreads();
        }
        if (tid == 0 && s2[0] != 0.f) grand += s1[0] / s2[0];
        __syncthreads();
    }
    if (tid == 0) out[0] = -grand / 32.0f;   // /M/2 with M=16
}

// ---------------- launch ----------------
extern "C" void kernel_launch(void* const* d_in, const int* in_sizes, int n_in,
                              void* d_out, int out_size) {
    const float* z    = (const float*)d_in[0];
    const float* spr  = (const float*)d_in[1];
    const float* f    = (const float*)d_in[2];
    const float* pag  = (const float*)d_in[3];
    const float* psp  = (const float*)d_in[4];
    const float* zmix = (const float*)d_in[5];
    const float* base = (const float*)d_in[6];
    float* out = (float*)d_out;

    const int SMEM_RMAX = 33792 * 4;             // 135168 B
    const int SMEM_MAIN = 50688 * 4 + 3072;      // 205824 B
    cudaFuncSetAttribute(rmax_kernel, cudaFuncAttributeMaxDynamicSharedMemorySize, SMEM_RMAX);
    cudaFuncSetAttribute(main_kernel, cudaFuncAttributeMaxDynamicSharedMemorySize, SMEM_MAIN);

    pack_kernel<<<128, 256>>>(base);
    rmax_kernel<<<dim3(64, 2), 512, SMEM_RMAX>>>(f, spr, pag, psp);
    merge_kernel<<<16, 256>>>();
    main_kernel<<<dim3(64, 2), 512, SMEM_MAIN>>>(z, spr, f, zmix);
    reduce_kernel<<<1, 256>>>(out);
}

// round 7
// speedup vs baseline: 1.5196x; 1.5196x over previous
#include <cuda_runtime.h>
#include <math.h>

// ---------------- problem constants ----------------
#define NB 4096
#define ND 128
#define NTILE 64
#define NPAIR 2080
#define INV_TEMP 14.285714285714285714f          // 1/0.07
#define KE 20.609929155556619f                   // INV_TEMP * log2(e)
#define LN2 0.69314718055994531f

// ---------------- device scratch (no allocs) ----------------
__device__ float g_Rf[2][NB];
__device__ float g_Rs[2][NB];
__device__ float g_RfM[NB];
__device__ float g_RsM[NB];
__device__ unsigned g_baseBits[32768];           // [256 rows][128 words]
__device__ float g_part[NTILE][NB * 6];          // [slot][row*6+q]   6.29 MB
__device__ float g_sum[NB * 6];

// ---------------- small helpers ----------------
__device__ __forceinline__ unsigned long long ffma2(unsigned long long a,
                                                    unsigned long long b,
                                                    unsigned long long c) {
    unsigned long long d;
    asm("fma.rn.f32x2 %0, %1, %2, %3;" : "=l"(d) : "l"(a), "l"(b), "l"(c));
    return d;
}
__device__ __forceinline__ float red2(unsigned long long v) {
    float lo = __uint_as_float((unsigned)v);
    float hi = __uint_as_float((unsigned)(v >> 32));
    return lo + hi;
}
__device__ __forceinline__ float ex2f(float x) {
    float r; asm("ex2.approx.ftz.f32 %0, %1;" : "=f"(r) : "f"(x)); return r;
}
__device__ __forceinline__ float lg2f(float x) {
    float r; asm("lg2.approx.ftz.f32 %0, %1;" : "=f"(r) : "f"(x)); return r;
}

// ---------------- smem tile loaders (512-thread blocks) ----------------
// A tile: 64 rows x 128 k -> 64 k-pair slices, pitch 132 floats.
__device__ __forceinline__ void load_A(float* dst, const float* __restrict__ src,
                                       int g0, int tid) {
    for (int idx = tid; idx < 2048; idx += 512) {
        int row = idx >> 5, dv = idx & 31;
        float4 v = *(const float4*)(src + (size_t)(g0 + row) * ND + (dv << 2));
        int t = row >> 2, h = (row >> 1) & 1, par = row & 1;
        int cbase = ((h << 4) + t) * 4 + par * 2;
        dst[(2 * dv) * 132 + cbase]         = v.x;
        dst[(2 * dv) * 132 + cbase + 1]     = v.y;
        dst[(2 * dv + 1) * 132 + cbase]     = v.z;
        dst[(2 * dv + 1) * 132 + cbase + 1] = v.w;
    }
}

// B tile: 64 cols x 128 k row-major, pitch 132 floats.
__device__ __forceinline__ void load_B(float* dst, const float* __restrict__ src,
                                       int j0, int tid) {
    for (int idx = tid; idx < 2048; idx += 512) {
        int n = idx >> 5, dv = idx & 31;
        *(float4*)(dst + n * 132 + (dv << 2)) =
            *(const float4*)(src + (size_t)(j0 + n) * ND + (dv << 2));
    }
}

// 64x64x128 gemm, 4x4 per-thread tile, f32x2 FMAs, 256-thread group.
__device__ __forceinline__ void gemm44(const float* __restrict__ A,
                                       const float* __restrict__ B,
                                       int ty, int tx,
                                       unsigned long long acc[16]) {
#pragma unroll
    for (int i = 0; i < 16; i++) acc[i] = 0ull;
    const float* ap = A + ty * 4;
    const float* bp = B + tx * 4 * 132;
#pragma unroll 4
    for (int q = 0; q < 32; q++) {
        const float* s = ap + (2 * q) * 132;
        ulonglong2 c0 = *(const ulonglong2*)(s);
        ulonglong2 c1 = *(const ulonglong2*)(s + 64);
        ulonglong2 d0 = *(const ulonglong2*)(s + 132);
        ulonglong2 d1 = *(const ulonglong2*)(s + 196);
        unsigned long long aL[4] = {c0.x, c0.y, c1.x, c1.y};
        unsigned long long aH[4] = {d0.x, d0.y, d1.x, d1.y};
        unsigned long long bL[4], bH[4];
#pragma unroll
        for (int c = 0; c < 4; c++) {
            ulonglong2 cb = *(const ulonglong2*)(bp + c * 132 + 4 * q);
            bL[c] = cb.x; bH[c] = cb.y;
        }
#pragma unroll
        for (int r = 0; r < 4; r++)
#pragma unroll
            for (int c = 0; c < 4; c++)
                acc[r * 4 + c] = ffma2(aL[r], bL[c], acc[r * 4 + c]);
#pragma unroll
        for (int r = 0; r < 4; r++)
#pragma unroll
            for (int c = 0; c < 4; c++)
                acc[r * 4 + c] = ffma2(aH[r], bH[c], acc[r * 4 + c]);
    }
}

// ---------------- kernel 0: pack neglect-base mask to bits ----------------
__global__ void pack_kernel(const float* __restrict__ base) {
    int w = blockIdx.x * 256 + threadIdx.x;
    const float* p = base + (size_t)w * 32;
    unsigned bits = 0;
#pragma unroll
    for (int b = 0; b < 32; b++) bits |= (p[b] > 0.f) ? (1u << b) : 0u;
    g_baseBits[w] = bits;
}

// ---------------- kernel 1: pool row-maxes ----------------
__global__ void __launch_bounds__(512, 1)
rmax_kernel(const float* __restrict__ f, const float* __restrict__ spr,
            const float* __restrict__ pag, const float* __restrict__ psp) {
    extern __shared__ float sm[];
    int tid = threadIdx.x;
    int grp = tid >> 8, t = tid & 255, tx = t >> 4, ty = t & 15;
    int g0 = blockIdx.x * 64, p0 = blockIdx.y * 512;
    float* A0 = sm;
    float* A1 = sm + 8448;
    float* B0 = sm + 16896;
    float* B1 = sm + 25344;

    load_A(A0, f, g0, tid);
    load_A(A1, spr, g0, tid);

    float rm[4];
#pragma unroll
    for (int r = 0; r < 4; r++) rm[r] = -1e30f;

    for (int jt = 0; jt < 8; jt++) {
        __syncthreads();
        load_B(B0, pag, p0 + jt * 64, tid);
        load_B(B1, psp, p0 + jt * 64, tid);
        __syncthreads();
        unsigned long long acc[16];
        gemm44(grp ? A1 : A0, grp ? B1 : B0, ty, tx, acc);
#pragma unroll
        for (int r = 0; r < 4; r++)
#pragma unroll
            for (int c = 0; c < 4; c++)
                rm[r] = fmaxf(rm[r], red2(acc[r * 4 + c]));
    }
    __syncthreads();
#pragma unroll
    for (int r = 0; r < 4; r++)
        sm[grp * 1024 + (ty * 4 + r) * 16 + tx] = rm[r];
    __syncthreads();
    if (tid < 64) {
        float mf = -1e30f, ms = -1e30f;
        for (int k = 0; k < 16; k++) {
            mf = fmaxf(mf, sm[tid * 16 + k]);
            ms = fmaxf(ms, sm[1024 + tid * 16 + k]);
        }
        g_Rf[blockIdx.y][g0 + tid] = mf;
        g_Rs[blockIdx.y][g0 + tid] = ms;
    }
}

// ---------------- kernel 1b: merge pool halves ----------------
__global__ void merge_kernel() {
    int i = blockIdx.x * 256 + threadIdx.x;
    g_RfM[i] = fmaxf(g_Rf[0][i], g_Rf[1][i]);
    g_RsM[i] = fmaxf(g_Rs[0][i], g_Rs[1][i]);
}

// ---------------- kernel 2: symmetric tile-pair pass ----------------
// grid = 2080 tile-pairs (a<=b). Each pair computes the 64x64 tile of all 4
// grams ONCE and accumulates both row-side (rows of a -> g_part[b]) and
// col-side (rows of b -> g_part[a]) per-row state. Masks are symmetric except
// the neglect-base bit, handled via a transposed lookup.
__global__ void __launch_bounds__(512, 1)
pair_kernel(const float* __restrict__ z, const float* __restrict__ spr,
            const float* __restrict__ f, const float* __restrict__ zmix) {
    extern __shared__ float sm[];
    int tid = threadIdx.x;
    int grp = tid >> 8, t = tid & 255, tx = t >> 4, ty = t & 15;

    // decode pair index -> (a, b), a <= b
    int p = blockIdx.x, a = 0;
    while (p >= NTILE - a) { p -= NTILE - a; a++; }
    int b = a + p;
    int g0 = a * 64, j0 = b * 64;

    float* AF = sm;
    float* ASP = sm + 8448;
    float* AZ = sm + 16896;
    float* AM = sm + 25344;
    float* B0 = sm + 33792;
    float* B1 = sm + 42240;
    unsigned* maskA = (unsigned*)(sm + 50688);
    unsigned* maskE = maskA + 256;
    unsigned* maskN = maskA + 512;
    unsigned* maskNT = maskA + 768;
    float* RED = sm + 33792;           // reduction slabs, reuse B region later

    load_A(AF, f, g0, tid);
    load_A(ASP, spr, g0, tid);
    load_A(AZ, z, g0, tid);
    load_A(AM, zmix, g0, tid);
    load_B(B0, f, j0, tid);
    load_B(B1, spr, j0, tid);
    __syncthreads();

    // ---- pass 1: masks ----
    {
        unsigned long long acc[16];
        gemm44(grp ? ASP : AF, grp ? B1 : B0, ty, tx, acc);

        const float* Rv = grp ? g_RsM : g_RfM;
        float Rr[4], Rc[4];
#pragma unroll
        for (int r = 0; r < 4; r++) Rr[r] = Rv[g0 + ty * 4 + r];
#pragma unroll
        for (int c = 0; c < 4; c++) Rc[c] = Rv[j0 + tx * 4 + c];

        unsigned neqm = (a == b && tx == ty) ? ~0x8421u : ~0u;
        unsigned bM = 0;
#pragma unroll
        for (int r = 0; r < 4; r++)
#pragma unroll
            for (int c = 0; c < 4; c++) {
                float v = red2(acc[r * 4 + c]);
                if ((Rr[r] < v) | (Rc[c] < v)) bM |= 1u << (r * 4 + c);
            }
        bM &= neqm;

        if (grp == 0) {
            // row-side neglect bits: base[i%256][j]
            int wcol = (j0 + tx * 4) >> 5;
            int shj = (tx * 4) & 31;
            unsigned nbBits = 0;
#pragma unroll
            for (int r = 0; r < 4; r++) {
                int i = g0 + ty * 4 + r;
                unsigned nbw = (g_baseBits[(i & 255) * 128 + wcol] >> shj) & 15u;
                nbBits |= nbw << (4 * r);
            }
            // col-side (transposed) neglect bits: base[j%256][i]
            int iw = (g0 + ty * 4) >> 5;
            int shi = (ty * 4) & 31;
            unsigned nbT = 0;
#pragma unroll
            for (int c = 0; c < 4; c++) {
                int j = j0 + tx * 4 + c;
                unsigned w4 = (g_baseBits[(j & 255) * 128 + iw] >> shi) & 15u;
#pragma unroll
                for (int r = 0; r < 4; r++)
                    nbT |= ((w4 >> r) & 1u) << (r * 4 + c);
            }
            maskA[t] = bM;
            maskN[t] = bM | (nbBits & neqm);
            maskNT[t] = bM | (nbT & neqm);
        } else {
            maskE[t] = bM;
        }
    }

    // ---- pass 2: logits ----
    __syncthreads();
    load_B(B0, z, j0, tid);
    load_B(B1, zmix, j0, tid);
    __syncthreads();

    unsigned long long acc[16];
    gemm44(grp ? AM : AZ, grp ? B1 : B0, ty, tx, acc);

    unsigned bA = maskA[t], bE = maskE[t], bN = maskN[t], bNT = maskNT[t];
    float st0[4], st1[4], st0T[4], st1T[4];
#pragma unroll
    for (int r = 0; r < 4; r++) { st0[r] = 0.f; st1[r] = 0.f; st0T[r] = 0.f; st1T[r] = 0.f; }

#pragma unroll
    for (int r = 0; r < 4; r++)
#pragma unroll
        for (int c = 0; c < 4; c++) {
            int idx = r * 4 + c;
            float v = red2(acc[idx]);
            float w = (((bA >> idx) & 1u) ? 1.0f : 0.0f) +
                      (((bE >> idx) & 1u) ? 0.5f : 0.0f);
            float wv = w * v;
            float e = ex2f(KE * (v - 1.0f));
            st1[r] += wv;
            st0[r] += ((bN >> idx) & 1u) ? e : 0.f;
            st1T[c] += wv;
            st0T[c] += ((bNT >> idx) & 1u) ? e : 0.f;
        }

    // ---- write reduction slabs ----
    __syncthreads();   // B tiles no longer needed; RED overlays them
    if (grp == 0) {
#pragma unroll
        for (int r = 0; r < 4; r++) {
            int row = ty * 4 + r;
            float pA = (float)__popc((bA >> (4 * r)) & 15u);
            float pE = (float)__popc((bE >> (4 * r)) & 15u);
            RED[0 * 1024 + row * 16 + tx] = st0[r];            // Zz
            RED[1 * 1024 + row * 16 + tx] = st1[r];            // Sz
            RED[2 * 1024 + row * 16 + tx] = pA + 0.5f * pE;    // ws
            RED[3 * 1024 + row * 16 + tx] = pA;                // vc
        }
#pragma unroll
        for (int c = 0; c < 4; c++) {
            int row = tx * 4 + c;
            unsigned cmask = 0x1111u << c;
            float pA = (float)__popc(bA & cmask);
            float pE = (float)__popc(bE & cmask);
            RED[6144 + 0 * 1024 + row * 16 + ty] = st0T[c];          // ZzT
            RED[6144 + 1 * 1024 + row * 16 + ty] = st1T[c];          // SzT
            RED[6144 + 2 * 1024 + row * 16 + ty] = pA + 0.5f * pE;   // wsT
            RED[6144 + 3 * 1024 + row * 16 + ty] = pA;               // vcT
        }
    } else {
#pragma unroll
        for (int r = 0; r < 4; r++) {
            int row = ty * 4 + r;
            RED[4 * 1024 + row * 16 + tx] = st0[r];            // Zm
            RED[5 * 1024 + row * 16 + tx] = st1[r];            // Sm
        }
#pragma unroll
        for (int c = 0; c < 4; c++) {
            int row = tx * 4 + c;
            RED[6144 + 4 * 1024 + row * 16 + ty] = st0T[c];    // ZmT
            RED[6144 + 5 * 1024 + row * 16 + ty] = st1T[c];    // SmT
        }
    }
    __syncthreads();

    // ---- final per-row sums -> g_part ----
    if (tid < 64) {
        float s[6] = {0.f, 0.f, 0.f, 0.f, 0.f, 0.f};
        for (int k = 0; k < 16; k++)
#pragma unroll
            for (int q = 0; q < 6; q++) s[q] += RED[q * 1024 + tid * 16 + k];
        float* d = &g_part[b][(size_t)(g0 + tid) * 6];
        d[0] = s[0]; d[1] = s[4]; d[2] = s[1]; d[3] = s[5]; d[4] = s[2]; d[5] = s[3];
    } else if (tid < 128 && a != b) {
        int rr = tid - 64;
        float s[6] = {0.f, 0.f, 0.f, 0.f, 0.f, 0.f};
        for (int k = 0; k < 16; k++)
#pragma unroll
            for (int q = 0; q < 6; q++) s[q] += RED[6144 + q * 1024 + rr * 16 + k];
        float* d = &g_part[a][(size_t)(j0 + rr) * 6];
        d[0] = s[0]; d[1] = s[4]; d[2] = s[1]; d[3] = s[5]; d[4] = s[2]; d[5] = s[3];
    }
}

// ---------------- kernel 2b: sum over the 64 slots ----------------
__global__ void slotsum_kernel() {
    int i = blockIdx.x * 256 + threadIdx.x;   // 24576 elements
    float s = 0.f;
    for (int sl = 0; sl < NTILE; sl++) s += g_part[sl][i];
    g_sum[i] = s;
}

// ---------------- kernel 3: final scalar reduction ----------------
__global__ void reduce_kernel(float* __restrict__ out) {
    __shared__ float s1[256], s2[256];
    int tid = threadIdx.x;
    float grand = 0.f;
    for (int m = 0; m < 16; m++) {
        int i = m * 256 + tid;
        float q[6];
#pragma unroll
        for (int qn = 0; qn < 6; qn++) q[qn] = g_sum[(size_t)i * 6 + qn];
        float Zz = q[0], Zm = q[1], Sz = q[2], Sm = q[3], w = q[4], vcc = q[5];
        float num = 0.f, den = 0.f;
        if (vcc > 0.5f) {
            float lzz = INV_TEMP + LN2 * lg2f(Zz);
            float lzm = INV_TEMP + LN2 * lg2f(Zm);
            num = INV_TEMP * (Sz + Sm) - w * (lzz + lzm);
            den = w;
        }
        s1[tid] = num;
        s2[tid] = den;
        __syncthreads();
        for (int off = 128; off > 0; off >>= 1) {
            if (tid < off) { s1[tid] += s1[tid + off]; s2[tid] += s2[tid + off]; }
            __syncthreads();
        }
        if (tid == 0 && s2[0] != 0.f) grand += s1[0] / s2[0];
        __syncthreads();
    }
    if (tid == 0) out[0] = -grand / 32.0f;   // /M/2 with M=16
}

// ---------------- launch ----------------
extern "C" void kernel_launch(void* const* d_in, const int* in_sizes, int n_in,
                              void* d_out, int out_size) {
    const float* z    = (const float*)d_in[0];
    const float* spr  = (const float*)d_in[1];
    const float* f    = (const float*)d_in[2];
    const float* pag  = (const float*)d_in[3];
    const float* psp  = (const float*)d_in[4];
    const float* zmix = (const float*)d_in[5];
    const float* base = (const float*)d_in[6];
    float* out = (float*)d_out;

    const int SMEM_RMAX = 33792 * 4;             // 135168 B
    const int SMEM_PAIR = 50688 * 4 + 4096;      // 206848 B
    cudaFuncSetAttribute(rmax_kernel, cudaFuncAttributeMaxDynamicSharedMemorySize, SMEM_RMAX);
    cudaFuncSetAttribute(pair_kernel, cudaFuncAttributeMaxDynamicSharedMemorySize, SMEM_PAIR);

    pack_kernel<<<128, 256>>>(base);
    rmax_kernel<<<dim3(64, 2), 512, SMEM_RMAX>>>(f, spr, pag, psp);
    merge_kernel<<<16, 256>>>();
    pair_kernel<<<NPAIR, 512, SMEM_PAIR>>>(z, spr, f, zmix);
    slotsum_kernel<<<96, 256>>>();
    reduce_kernel<<<1, 256>>>(out);
}